// round 12
// baseline (speedup 1.0000x reference)
#include <cuda_runtime.h>
#include <cstdint>

#define HVAL 256
#define HINGE 100.0f
#define NB 888            // b-groups per sweep (148 SMs * 6)
#define NSTAGE 3

// Single-instruction approximate sqrt (MUFU.SQRT). sqrt.approx(+0) = +0.
__device__ __forceinline__ float asqrt(float x) {
    float r;
    asm("sqrt.approx.f32 %0, %1;" : "=f"(r) : "f"(x));
    return r;
}

__device__ __forceinline__ void cp_async16(uint32_t smem_dst, const void* gmem_src) {
    asm volatile("cp.async.cg.shared.global [%0], [%1], 16;\n"
                 :: "r"(smem_dst), "l"(gmem_src));
}
__device__ __forceinline__ void cp_commit() {
    asm volatile("cp.async.commit_group;\n");
}
template<int N>
__device__ __forceinline__ void cp_wait() {
    asm volatile("cp.async.wait_group %0;\n" :: "n"(N));
}

// 128-thread CTAs, 12/SM: each CTA owns a fixed half of the h-range and
// pipelines over b. Tile-half = 128 elements: 288 rot float4 + 96 pos float4.
__global__ __launch_bounds__(128, 12)
void traj_cost_kernel(const float* __restrict__ pos,   // [B,H,3]
                      const float* __restrict__ rot,   // [B,H,3,3]
                      const float* __restrict__ gpos,  // [H,3]
                      const float* __restrict__ grot,  // [H,3,3]
                      float* __restrict__ out,         // [3,B*H]
                      int B)
{
    // 3-stage ring: (1152 + 384) floats * 4 B = 6.1 KB per stage, 18.4 KB total
    __shared__ float s_rot[NSTAGE][128 * 9];
    __shared__ float s_pos[NSTAGE][128 * 3];

    const int tid   = threadIdx.x;
    const int half  = blockIdx.x & 1;          // which h-half this CTA owns
    const int hbase = half * 128;
    const int h     = hbase + tid;

    // ---- Goal data: once into registers; precompute negated otg ----
    float G[9], notg[3];
    #pragma unroll
    for (int i = 0; i < 9; i++) G[i] = __ldg(&grot[h * 9 + i]);
    {
        float pg0 = __ldg(&gpos[h * 3 + 0]);
        float pg1 = __ldg(&gpos[h * 3 + 1]);
        float pg2 = __ldg(&gpos[h * 3 + 2]);
        #pragma unroll
        for (int i = 0; i < 3; i++)
            notg[i] = -fmaf(G[i], pg0, fmaf(G[3 + i], pg1, G[6 + i] * pg2));
    }

    uint32_t srot[NSTAGE], spos[NSTAGE];
    #pragma unroll
    for (int s = 0; s < NSTAGE; s++) {
        srot[s] = (uint32_t)__cvta_generic_to_shared(s_rot[s]);
        spos[s] = (uint32_t)__cvta_generic_to_shared(s_pos[s]);
    }

    // 32-bit float4 offsets (max 4.7M float4 < 2^31)
    const int b0 = blockIdx.x >> 1;            // starting b for this CTA
    int rof4 = b0 * 576 + half * 288;
    int pof4 = b0 * 192 + half * 96;
    int n    = b0 * HVAL + h;
    const int rstep = NB * 576;
    const int pstep = NB * 192;
    const int nstep = NB * HVAL;
    const int BH    = B * HVAL;

    const float4* rbase = reinterpret_cast<const float4*>(rot);
    const float4* pbase = reinterpret_cast<const float4*>(pos);

    float* __restrict__ out0 = out;
    float* __restrict__ out1 = out + BH;
    float* __restrict__ out2 = out + 2 * BH;

    // Stage one tile-half: 288 rot f4 (2 full passes + 32-lane tail) + 96 pos f4
    auto stage = [&](int s, int ro, int po) {
        cp_async16(srot[s] + (uint32_t)(tid      ) * 16, rbase + ro + tid);
        cp_async16(srot[s] + (uint32_t)(tid + 128) * 16, rbase + ro + tid + 128);
        if (tid < 32)
            cp_async16(srot[s] + (uint32_t)(tid + 256) * 16, rbase + ro + tid + 256);
        if (tid < 96)
            cp_async16(spos[s] + (uint32_t)tid * 16, pbase + po + tid);
        cp_commit();
    };

    int b = b0;

    // Prologue: prefetch distance 2
    stage(0, rof4, pof4);
    if (b + NB < B)
        stage(1, rof4 + rstep, pof4 + pstep);

    int buf = 0;
    for (; b < B; b += NB) {
        if (b + NB < B) cp_wait<1>(); else cp_wait<0>();
        __syncthreads();   // couples only 4 warps now

        if (b + 2 * NB < B)
            stage((buf + 2) % NSTAGE, rof4 + 2 * rstep, pof4 + 2 * pstep);

        float R[9], p[3];
        #pragma unroll
        for (int i = 0; i < 9; i++) R[i] = s_rot[buf][tid * 9 + i];
        #pragma unroll
        for (int i = 0; i < 3; i++) p[i] = s_pos[buf][tid * 3 + i];

        // t[i] = (R^T p)[i] - otg[i]
        float t0 = fmaf(R[0], p[0], fmaf(R[3], p[1], fmaf(R[6], p[2], notg[0])));
        float t1 = fmaf(R[1], p[0], fmaf(R[4], p[1], fmaf(R[7], p[2], notg[1])));
        float t2 = fmaf(R[2], p[0], fmaf(R[5], p[1], fmaf(R[8], p[2], notg[2])));
        float pos_err   = fmaf(t0, t0, fmaf(t1, t1, t2 * t2));
        float goal_dist = asqrt(pos_err);

        // m' = G^T R - I (identity folded into FMA seed); rn[i] = ||row i||
        float rn[3];
        #pragma unroll
        for (int i = 0; i < 3; i++) {
            float rsq = 0.0f;
            #pragma unroll
            for (int j = 0; j < 3; j++) {
                float seed = (i == j) ? -1.0f : 0.0f;
                float m = fmaf(G[i], R[j],
                          fmaf(G[3 + i], R[3 + j],
                          fmaf(G[6 + i], R[6 + j], seed)));
                rsq = fmaf(m, m, rsq);
            }
            rn[i] = asqrt(rsq);
        }

        float rn_sum       = rn[0] + rn[1] + rn[2];
        float rot_err_norm = asqrt(fmaf(rn[0], rn[0], fmaf(rn[1], rn[1], rn[2] * rn[2])));
        float sq_rot = (goal_dist <= HINGE) ? rn_sum : 0.0f;  // sqrt(rn_sum^2) = rn_sum

        __stcs(out0 + n, sq_rot + goal_dist);   // WEIGHT = (1,1)
        __stcs(out1 + n, rot_err_norm);
        __stcs(out2 + n, goal_dist);

        buf = (buf + 1) % NSTAGE;
        rof4 += rstep;
        pof4 += pstep;
        n    += nstep;
    }
}

extern "C" void kernel_launch(void* const* d_in, const int* in_sizes, int n_in,
                              void* d_out, int out_size) {
    // Bind inputs BY SIZE (robust to harness ordering):
    //   H*3 -> gpos, H*9 -> grot, B*H*3 -> pos, B*H*9 -> rot
    int idx[4] = {0, 1, 2, 3};
    for (int i = 1; i < 4; i++) {
        int v = idx[i];
        int j = i - 1;
        while (j >= 0 && in_sizes[idx[j]] > in_sizes[v]) { idx[j + 1] = idx[j]; j--; }
        idx[j + 1] = v;
    }
    const float* gpos = (const float*)d_in[idx[0]];
    const float* grot = (const float*)d_in[idx[1]];
    const float* pos  = (const float*)d_in[idx[2]];
    const float* rot  = (const float*)d_in[idx[3]];

    const int H = in_sizes[idx[0]] / 3;          // 256
    const int B = in_sizes[idx[3]] / (9 * H);    // 8192

    float* out = (float*)d_out;
    traj_cost_kernel<<<2 * NB, 128>>>(pos, rot, gpos, grot, out, B);
}

// round 13
// speedup vs baseline: 1.0184x; 1.0184x over previous
#include <cuda_runtime.h>
#include <cstdint>

#define HVAL 256
#define HINGE 100.0f
#define NB 888            // b-groups per sweep (148 SMs * 6)
#define NSTAGE 3

// Single-instruction approximate sqrt (MUFU.SQRT). sqrt.approx(+0) = +0.
__device__ __forceinline__ float asqrt(float x) {
    float r;
    asm("sqrt.approx.f32 %0, %1;" : "=f"(r) : "f"(x));
    return r;
}

__device__ __forceinline__ void cp_async16(uint32_t smem_dst, const void* gmem_src) {
    asm volatile("cp.async.cg.shared.global [%0], [%1], 16;\n"
                 :: "r"(smem_dst), "l"(gmem_src));
}
__device__ __forceinline__ void cp_commit() {
    asm volatile("cp.async.commit_group;\n");
}
template<int N>
__device__ __forceinline__ void cp_wait() {
    asm volatile("cp.async.wait_group %0;\n" :: "n"(N));
}

// 128-thread CTAs, 12/SM. Each CTA owns a fixed h-half, pipelines over b with
// a 3-stage ring whose indices are ALL compile-time (loop unrolled by NSTAGE).
__global__ __launch_bounds__(128, 12)
void traj_cost_kernel(const float* __restrict__ pos,   // [B,H,3]
                      const float* __restrict__ rot,   // [B,H,3,3]
                      const float* __restrict__ gpos,  // [H,3]
                      const float* __restrict__ grot,  // [H,3,3]
                      float* __restrict__ out,         // [3,B*H]
                      int B)
{
    // 3-stage ring: (1152 + 384) floats * 4 B = 6.1 KB per stage, 18.4 KB total
    __shared__ float s_rot[NSTAGE][128 * 9];
    __shared__ float s_pos[NSTAGE][128 * 3];

    const int tid   = threadIdx.x;
    const int half  = blockIdx.x & 1;
    const int h     = half * 128 + tid;

    // ---- Goal data: once into registers; precompute negated otg ----
    float G[9], notg[3];
    #pragma unroll
    for (int i = 0; i < 9; i++) G[i] = __ldg(&grot[h * 9 + i]);
    {
        float pg0 = __ldg(&gpos[h * 3 + 0]);
        float pg1 = __ldg(&gpos[h * 3 + 1]);
        float pg2 = __ldg(&gpos[h * 3 + 2]);
        #pragma unroll
        for (int i = 0; i < 3; i++)
            notg[i] = -fmaf(G[i], pg0, fmaf(G[3 + i], pg1, G[6 + i] * pg2));
    }

    const int b0 = blockIdx.x >> 1;
    int rof4 = b0 * 576 + half * 288;   // float4 offsets, 32-bit safe
    int pof4 = b0 * 192 + half * 96;
    int n    = b0 * HVAL + h;
    const int rstep = NB * 576;
    const int pstep = NB * 192;
    const int nstep = NB * HVAL;
    const int BH    = B * HVAL;

    const float4* rbase = reinterpret_cast<const float4*>(rot);
    const float4* pbase = reinterpret_cast<const float4*>(pos);

    float* __restrict__ out0 = out;
    float* __restrict__ out1 = out + BH;
    float* __restrict__ out2 = out + 2 * BH;

    // Stage one tile-half into compile-time slot pointers.
    auto stage = [&](float* rd, float* pd, int ro, int po) {
        uint32_t sr = (uint32_t)__cvta_generic_to_shared(rd);
        uint32_t sp = (uint32_t)__cvta_generic_to_shared(pd);
        cp_async16(sr + (uint32_t)(tid      ) * 16, rbase + ro + tid);
        cp_async16(sr + (uint32_t)(tid + 128) * 16, rbase + ro + tid + 128);
        if (tid < 32)
            cp_async16(sr + (uint32_t)(tid + 256) * 16, rbase + ro + tid + 256);
        if (tid < 96)
            cp_async16(sp + (uint32_t)tid * 16, pbase + po + tid);
        cp_commit();
    };

    int b = b0;

    // Prologue: prefetch distance 2 into slots 0 and 1
    stage(s_rot[0], s_pos[0], rof4, pof4);
    if (b + NB < B)
        stage(s_rot[1], s_pos[1], rof4 + rstep, pof4 + pstep);

    while (b < B) {
        #pragma unroll
        for (int s = 0; s < NSTAGE; s++) {
            if (b >= B) break;

            if (b + NB < B) cp_wait<1>(); else cp_wait<0>();
            __syncthreads();

            if (b + 2 * NB < B) {
                const int s2 = (s + 2) % NSTAGE;     // constant after unroll
                stage(s_rot[s2], s_pos[s2], rof4 + 2 * rstep, pof4 + 2 * pstep);
            }

            float R[9], p[3];
            #pragma unroll
            for (int i = 0; i < 9; i++) R[i] = s_rot[s][tid * 9 + i];
            #pragma unroll
            for (int i = 0; i < 3; i++) p[i] = s_pos[s][tid * 3 + i];

            // t[i] = (R^T p)[i] - otg[i]
            float t0 = fmaf(R[0], p[0], fmaf(R[3], p[1], fmaf(R[6], p[2], notg[0])));
            float t1 = fmaf(R[1], p[0], fmaf(R[4], p[1], fmaf(R[7], p[2], notg[1])));
            float t2 = fmaf(R[2], p[0], fmaf(R[5], p[1], fmaf(R[8], p[2], notg[2])));
            float pos_err   = fmaf(t0, t0, fmaf(t1, t1, t2 * t2));
            float goal_dist = asqrt(pos_err);

            // m' = G^T R - I (identity folded into FMA seed)
            float rsq[3];
            #pragma unroll
            for (int i = 0; i < 3; i++) {
                float acc = 0.0f;
                #pragma unroll
                for (int j = 0; j < 3; j++) {
                    float seed = (i == j) ? -1.0f : 0.0f;
                    float m = fmaf(G[i], R[j],
                              fmaf(G[3 + i], R[3 + j],
                              fmaf(G[6 + i], R[6 + j], seed)));
                    acc = fmaf(m, m, acc);
                }
                rsq[i] = acc;
            }
            float rn0 = asqrt(rsq[0]);
            float rn1 = asqrt(rsq[1]);
            float rn2 = asqrt(rsq[2]);
            float rn_sum = rn0 + rn1 + rn2;
            // ||rn||^2 == rsq0+rsq1+rsq2 exactly (row norms squared again)
            float rot_err_norm = asqrt(rsq[0] + rsq[1] + rsq[2]);
            float sq_rot = (goal_dist <= HINGE) ? rn_sum : 0.0f;

            __stcs(out0 + n, sq_rot + goal_dist);   // WEIGHT = (1,1)
            __stcs(out1 + n, rot_err_norm);
            __stcs(out2 + n, goal_dist);

            b    += NB;
            rof4 += rstep;
            pof4 += pstep;
            n    += nstep;
        }
    }
}

extern "C" void kernel_launch(void* const* d_in, const int* in_sizes, int n_in,
                              void* d_out, int out_size) {
    // Bind inputs BY SIZE (robust to harness ordering):
    //   H*3 -> gpos, H*9 -> grot, B*H*3 -> pos, B*H*9 -> rot
    int idx[4] = {0, 1, 2, 3};
    for (int i = 1; i < 4; i++) {
        int v = idx[i];
        int j = i - 1;
        while (j >= 0 && in_sizes[idx[j]] > in_sizes[v]) { idx[j + 1] = idx[j]; j--; }
        idx[j + 1] = v;
    }
    const float* gpos = (const float*)d_in[idx[0]];
    const float* grot = (const float*)d_in[idx[1]];
    const float* pos  = (const float*)d_in[idx[2]];
    const float* rot  = (const float*)d_in[idx[3]];

    const int H = in_sizes[idx[0]] / 3;          // 256
    const int B = in_sizes[idx[3]] / (9 * H);    // 8192

    float* out = (float*)d_out;
    traj_cost_kernel<<<2 * NB, 128>>>(pos, rot, gpos, grot, out, B);
}

// round 15
// speedup vs baseline: 1.0198x; 1.0014x over previous
#include <cuda_runtime.h>
#include <cstdint>

#define HVAL 256
#define HINGE 100.0f
#define NB 888            // b-groups per sweep (148 SMs * 6)
#define NSTAGE 3

// Single-instruction approximate sqrt (MUFU.SQRT). sqrt.approx(+0) = +0.
__device__ __forceinline__ float asqrt(float x) {
    float r;
    asm("sqrt.approx.f32 %0, %1;" : "=f"(r) : "f"(x));
    return r;
}

__device__ __forceinline__ void cp_async16(uint32_t smem_dst, const void* gmem_src) {
    asm volatile("cp.async.cg.shared.global [%0], [%1], 16;\n"
                 :: "r"(smem_dst), "l"(gmem_src));
}
__device__ __forceinline__ void cp_commit() {
    asm volatile("cp.async.commit_group;\n");
}
template<int N>
__device__ __forceinline__ void cp_wait() {
    asm volatile("cp.async.wait_group %0;\n" :: "n"(N));
}

// 128-thread CTAs, 12/SM. 3-stage ring, compile-time slot indices.
// Per-iteration order: syncA (slot retire) -> stage(i+2) -> per-thread wait
// -> syncB (publish) -> consume. Prefetch is in flight BEFORE the wait, and
// cross-thread visibility is re-established by syncB (the R12 race fix).
__global__ __launch_bounds__(128, 12)
void traj_cost_kernel(const float* __restrict__ pos,   // [B,H,3]
                      const float* __restrict__ rot,   // [B,H,3,3]
                      const float* __restrict__ gpos,  // [H,3]
                      const float* __restrict__ grot,  // [H,3,3]
                      float* __restrict__ out,         // [3,B*H]
                      int B)
{
    __shared__ float s_rot[NSTAGE][128 * 9];
    __shared__ float s_pos[NSTAGE][128 * 3];

    const int tid  = threadIdx.x;
    const int half = blockIdx.x & 1;
    const int h    = half * 128 + tid;

    // ---- Goal data: once into registers; precompute negated otg ----
    float G[9], notg[3];
    #pragma unroll
    for (int i = 0; i < 9; i++) G[i] = __ldg(&grot[h * 9 + i]);
    {
        float pg0 = __ldg(&gpos[h * 3 + 0]);
        float pg1 = __ldg(&gpos[h * 3 + 1]);
        float pg2 = __ldg(&gpos[h * 3 + 2]);
        #pragma unroll
        for (int i = 0; i < 3; i++)
            notg[i] = -fmaf(G[i], pg0, fmaf(G[3 + i], pg1, G[6 + i] * pg2));
    }

    const int b0 = blockIdx.x >> 1;
    int rof4 = b0 * 576 + half * 288;   // float4 offsets, 32-bit safe
    int pof4 = b0 * 192 + half * 96;
    int n    = b0 * HVAL + h;
    const int rstep = NB * 576;
    const int pstep = NB * 192;
    const int nstep = NB * HVAL;
    const int BH    = B * HVAL;

    const float4* rbase = reinterpret_cast<const float4*>(rot);
    const float4* pbase = reinterpret_cast<const float4*>(pos);

    float* __restrict__ out0 = out;
    float* __restrict__ out1 = out + BH;
    float* __restrict__ out2 = out + 2 * BH;

    auto stage = [&](float* rd, float* pd, int ro, int po) {
        uint32_t sr = (uint32_t)__cvta_generic_to_shared(rd);
        uint32_t sp = (uint32_t)__cvta_generic_to_shared(pd);
        cp_async16(sr + (uint32_t)(tid      ) * 16, rbase + ro + tid);
        cp_async16(sr + (uint32_t)(tid + 128) * 16, rbase + ro + tid + 128);
        if (tid < 32)
            cp_async16(sr + (uint32_t)(tid + 256) * 16, rbase + ro + tid + 256);
        if (tid < 96)
            cp_async16(sp + (uint32_t)tid * 16, pbase + po + tid);
        cp_commit();
    };

    int b = b0;

    // Prologue: prefetch distance 2 into slots 0 and 1
    stage(s_rot[0], s_pos[0], rof4, pof4);
    if (b + NB < B)
        stage(s_rot[1], s_pos[1], rof4 + rstep, pof4 + pstep);

    while (b < B) {
        #pragma unroll
        for (int s = 0; s < NSTAGE; s++) {
            if (b >= B) break;

            // A) all warps finished consuming tile i-1 -> its slot is free
            __syncthreads();

            // stage tile i+2 into the retired slot BEFORE waiting
            const bool has1 = (b + NB     < B);
            const bool has2 = (b + 2 * NB < B);
            if (has2) {
                const int s2 = (s + 2) % NSTAGE;     // constant after unroll
                stage(s_rot[s2], s_pos[s2], rof4 + 2 * rstep, pof4 + 2 * pstep);
            }

            // per-thread wait: own tile-i copies complete
            if (has2)      cp_wait<2>();
            else if (has1) cp_wait<1>();
            else           cp_wait<0>();

            // B) publish: ALL threads' tile-i copies are now visible
            __syncthreads();

            // consume tile i
            float R[9], p[3];
            #pragma unroll
            for (int i = 0; i < 9; i++) R[i] = s_rot[s][tid * 9 + i];
            #pragma unroll
            for (int i = 0; i < 3; i++) p[i] = s_pos[s][tid * 3 + i];

            // t[i] = (R^T p)[i] - otg[i]
            float t0 = fmaf(R[0], p[0], fmaf(R[3], p[1], fmaf(R[6], p[2], notg[0])));
            float t1 = fmaf(R[1], p[0], fmaf(R[4], p[1], fmaf(R[7], p[2], notg[1])));
            float t2 = fmaf(R[2], p[0], fmaf(R[5], p[1], fmaf(R[8], p[2], notg[2])));
            float pos_err   = fmaf(t0, t0, fmaf(t1, t1, t2 * t2));
            float goal_dist = asqrt(pos_err);

            // m' = G^T R - I (identity folded into FMA seed)
            float rsq[3];
            #pragma unroll
            for (int i = 0; i < 3; i++) {
                float acc = 0.0f;
                #pragma unroll
                for (int j = 0; j < 3; j++) {
                    float seed = (i == j) ? -1.0f : 0.0f;
                    float m = fmaf(G[i], R[j],
                              fmaf(G[3 + i], R[3 + j],
                              fmaf(G[6 + i], R[6 + j], seed)));
                    acc = fmaf(m, m, acc);
                }
                rsq[i] = acc;
            }
            float rn_sum = asqrt(rsq[0]) + asqrt(rsq[1]) + asqrt(rsq[2]);
            float rot_err_norm = asqrt(rsq[0] + rsq[1] + rsq[2]);
            float sq_rot = (goal_dist <= HINGE) ? rn_sum : 0.0f;

            __stcs(out0 + n, sq_rot + goal_dist);   // WEIGHT = (1,1)
            __stcs(out1 + n, rot_err_norm);
            __stcs(out2 + n, goal_dist);

            b    += NB;
            rof4 += rstep;
            pof4 += pstep;
            n    += nstep;
        }
    }
}

extern "C" void kernel_launch(void* const* d_in, const int* in_sizes, int n_in,
                              void* d_out, int out_size) {
    // Bind inputs BY SIZE (robust to harness ordering):
    //   H*3 -> gpos, H*9 -> grot, B*H*3 -> pos, B*H*9 -> rot
    int idx[4] = {0, 1, 2, 3};
    for (int i = 1; i < 4; i++) {
        int v = idx[i];
        int j = i - 1;
        while (j >= 0 && in_sizes[idx[j]] > in_sizes[v]) { idx[j + 1] = idx[j]; j--; }
        idx[j + 1] = v;
    }
    const float* gpos = (const float*)d_in[idx[0]];
    const float* grot = (const float*)d_in[idx[1]];
    const float* pos  = (const float*)d_in[idx[2]];
    const float* rot  = (const float*)d_in[idx[3]];

    const int H = in_sizes[idx[0]] / 3;          // 256
    const int B = in_sizes[idx[3]] / (9 * H);    // 8192

    float* out = (float*)d_out;
    traj_cost_kernel<<<2 * NB, 128>>>(pos, rot, gpos, grot, out, B);
}